// round 2
// baseline (speedup 1.0000x reference)
#include <cuda_runtime.h>

// Problem constants (shapes fixed by the dataset)
#define NCOLS 1024      // n1 - 1
#define C_LIM 1022      // n1 - 2 (columns actually summed)
#define R_LIM 32767     // n2 - 1 (rows actually summed)

#define NBLOCKS 2048
#define NTHREADS 256

// Scratch for per-block partials (no device allocation allowed)
__device__ float g_partials[NBLOCKS];

__global__ __launch_bounds__(NTHREADS)
void rosen_partial_kernel(const float* __restrict__ x,
                          const float* __restrict__ b) {
    // Iterate over idx = r*1024 + c, r in [0, R_LIM), c in [0, 1024),
    // predicating off c >= C_LIM (2/1024 lanes idle — cheaper than a divide).
    const unsigned int total = (unsigned int)R_LIM * NCOLS;  // 33,553,408 < 2^31
    const unsigned int stride = (unsigned int)NBLOCKS * NTHREADS;

    // y[r,c] = x[1 + r*1024 + c].  Pre-offset the pointer.
    const float* __restrict__ y0 = x + 1;

    float acc = 0.0f;
    #pragma unroll 4
    for (unsigned int idx = blockIdx.x * NTHREADS + threadIdx.x;
         idx < total; idx += stride) {
        unsigned int c = idx & (NCOLS - 1);
        if (c < C_LIM) {
            unsigned int base = idx - c;                 // r * 1024
            unsigned int cp = (c == 0) ? (NCOLS - 1) : (c - 1);
            float yi = __ldg(y0 + base + c);
            float yp = __ldg(y0 + base + cp);            // adjacent addr -> L1 hit
            float bb = __ldg(b + base + c);
            float d  = yi - yp * yp;
            acc = fmaf(bb * d, d, acc);
        }
    }

    // --- block reduction (warp shuffle + shared) ---
    #pragma unroll
    for (int off = 16; off > 0; off >>= 1)
        acc += __shfl_down_sync(0xFFFFFFFFu, acc, off);

    __shared__ float smem[NTHREADS / 32];
    int lane = threadIdx.x & 31;
    int warp = threadIdx.x >> 5;
    if (lane == 0) smem[warp] = acc;
    __syncthreads();

    if (warp == 0) {
        float v = (lane < NTHREADS / 32) ? smem[lane] : 0.0f;
        #pragma unroll
        for (int off = 4; off > 0; off >>= 1)
            v += __shfl_down_sync(0xFFFFFFFFu, v, off);
        if (lane == 0) g_partials[blockIdx.x] = v;
    }
}

__global__ __launch_bounds__(1024)
void rosen_final_kernel(const float* __restrict__ x,
                        const float* __restrict__ a,
                        const float* __restrict__ mu,
                        float* __restrict__ out) {
    __shared__ double sh[1024];
    int tid = threadIdx.x;
    double v = (double)g_partials[tid] + (double)g_partials[tid + 1024];
    sh[tid] = v;
    __syncthreads();
    #pragma unroll
    for (int off = 512; off > 0; off >>= 1) {
        if (tid < off) sh[tid] += sh[tid + off];
        __syncthreads();
    }
    if (tid == 0) {
        double dx = (double)x[0] - (double)mu[0];
        out[0] = (float)(-(double)a[0] * dx * dx - sh[0]);
    }
}

extern "C" void kernel_launch(void* const* d_in, const int* in_sizes, int n_in,
                              void* d_out, int out_size) {
    const float* x  = (const float*)d_in[0];
    const float* a  = (const float*)d_in[1];
    const float* b  = (const float*)d_in[2];
    const float* mu = (const float*)d_in[3];
    float* out = (float*)d_out;

    rosen_partial_kernel<<<NBLOCKS, NTHREADS>>>(x, b);
    rosen_final_kernel<<<1, 1024>>>(x, a, mu, out);
}

// round 3
// speedup vs baseline: 1.4153x; 1.4153x over previous
#include <cuda_runtime.h>

// Shapes fixed by the dataset: n1=1025, n2=32768
#define ROWLEN 1024          // n1 - 1 (row stride of y and b)
#define NROWS  32767         // n2 - 1 (rows summed)
// terms: c in [0, 1023)  (n1 - 2 = 1023 columns)  -- R2 bug was 1022!

#define NBLOCKS 2048
#define NTHREADS 256
#define WARPS_PER_BLOCK (NTHREADS / 32)
#define TOTAL_WARPS (NBLOCKS * WARPS_PER_BLOCK)

// Scratch for per-block partials (no device allocation allowed)
__device__ float g_partials[NBLOCKS];

// term(c) = b[r,c] * (x[p+c+1] - x[p+c]^2)^2,  p = r*1024, for c in [1,1022]
// term(0) = b[r,0] * (x[p+1]   - x[p+1024]^2)^2   (roll wrap: yprev = y[r,1023])
__global__ __launch_bounds__(NTHREADS)
void rosen_partial_kernel(const float* __restrict__ x,
                          const float* __restrict__ b) {
    const int lane = threadIdx.x & 31;
    const int wid  = threadIdx.x >> 5;
    const int gw   = blockIdx.x * WARPS_PER_BLOCK + wid;

    float acc = 0.0f;

    for (int r = gw; r < NROWS; r += TOTAL_WARPS) {
        const float*  xr = x + (size_t)r * ROWLEN;          // 16B-aligned (4096B stride)
        const float4* x4 = (const float4*)xr;
        const float4* b4 = (const float4*)(b + (size_t)r * ROWLEN);

        #pragma unroll
        for (int it = 0; it < 8; ++it) {
            const int v = it * 32 + lane;                   // vector index, 0..255
            float4 xa = __ldg(x4 + v);                      // xr[4v .. 4v+3]
            float4 bb = __ldg(b4 + v);                      // b[r, 4v .. 4v+3]

            // neighbor value xr[4v+4] for term c=4v+3
            float nb = __shfl_down_sync(0xFFFFFFFFu, xa.x, 1);
            if (lane == 31) nb = __ldg(xr + 4 * v + 4);     // in-bounds: <= xr[1024]

            // c = 4v   : pair (xa.x, xa.y), b=bb.x   -- v==0 handled via wrap below
            if (v > 0) {
                float d = fmaf(-xa.x, xa.x, xa.y);
                acc = fmaf(bb.x * d, d, acc);
            }
            // c = 4v+1 : pair (xa.y, xa.z)
            {
                float d = fmaf(-xa.y, xa.y, xa.z);
                acc = fmaf(bb.y * d, d, acc);
            }
            // c = 4v+2 : pair (xa.z, xa.w)
            {
                float d = fmaf(-xa.z, xa.z, xa.w);
                acc = fmaf(bb.z * d, d, acc);
            }
            // c = 4v+3 : pair (xa.w, nb); valid while c <= 1022  (v <= 254)
            if (v < 255) {
                float d = fmaf(-xa.w, xa.w, nb);
                acc = fmaf(bb.w * d, d, acc);
            }
            // c = 0 wrap term (lane 0 of first iteration only)
            if (v == 0) {
                float yw = __ldg(xr + 1024);                // y[r,1023]
                float d  = fmaf(-yw, yw, xa.y);             // xa.y = y[r,0]
                acc = fmaf(bb.x * d, d, acc);
            }
        }
    }

    // --- block reduction (warp shuffle + shared) ---
    #pragma unroll
    for (int off = 16; off > 0; off >>= 1)
        acc += __shfl_down_sync(0xFFFFFFFFu, acc, off);

    __shared__ float smem[WARPS_PER_BLOCK];
    if (lane == 0) smem[wid] = acc;
    __syncthreads();

    if (wid == 0) {
        float v = (lane < WARPS_PER_BLOCK) ? smem[lane] : 0.0f;
        #pragma unroll
        for (int off = 4; off > 0; off >>= 1)
            v += __shfl_down_sync(0xFFFFFFFFu, v, off);
        if (lane == 0) g_partials[blockIdx.x] = v;
    }
}

__global__ __launch_bounds__(256)
void rosen_final_kernel(const float* __restrict__ x,
                        const float* __restrict__ a,
                        const float* __restrict__ mu,
                        float* __restrict__ out) {
    __shared__ double sh[256];
    int t = threadIdx.x;
    double v = 0.0;
    #pragma unroll
    for (int i = 0; i < NBLOCKS / 256; ++i)
        v += (double)g_partials[t + 256 * i];
    sh[t] = v;
    __syncthreads();
    #pragma unroll
    for (int off = 128; off > 0; off >>= 1) {
        if (t < off) sh[t] += sh[t + off];
        __syncthreads();
    }
    if (t == 0) {
        double dx = (double)x[0] - (double)mu[0];
        out[0] = (float)(-(double)a[0] * dx * dx - sh[0]);
    }
}

extern "C" void kernel_launch(void* const* d_in, const int* in_sizes, int n_in,
                              void* d_out, int out_size) {
    const float* x  = (const float*)d_in[0];
    const float* a  = (const float*)d_in[1];
    const float* b  = (const float*)d_in[2];
    const float* mu = (const float*)d_in[3];
    float* out = (float*)d_out;

    rosen_partial_kernel<<<NBLOCKS, NTHREADS>>>(x, b);
    rosen_final_kernel<<<1, 256>>>(x, a, mu, out);
}